// round 1
// baseline (speedup 1.0000x reference)
#include <cuda_runtime.h>

#define K_DIM 2048
#define INV_F (1.0f / 2048.0f)
#define BM 128
#define BN 64
#define BK 16

// Scratch (no device allocation allowed): row sum-of-squares for x and w.
__device__ float g_x2[16384];
__device__ float g_w2[1024];

// One block per row; 128 threads; vectorized float4 loads over K=2048.
__global__ void rowsq_kernel(const float* __restrict__ a, int which) {
    int row = blockIdx.x;
    const float4* p = reinterpret_cast<const float4*>(a) + (size_t)row * (K_DIM / 4);
    float s = 0.f;
#pragma unroll
    for (int i = 0; i < (K_DIM / 4) / 128; ++i) {
        float4 v = p[threadIdx.x + i * 128];
        s += v.x * v.x + v.y * v.y + v.z * v.z + v.w * v.w;
    }
#pragma unroll
    for (int o = 16; o > 0; o >>= 1) s += __shfl_xor_sync(0xffffffffu, s, o);
    __shared__ float red[4];
    int wid = threadIdx.x >> 5;
    if ((threadIdx.x & 31) == 0) red[wid] = s;
    __syncthreads();
    if (threadIdx.x == 0) {
        float t = red[0] + red[1] + red[2] + red[3];
        if (which) g_x2[row] = t;
        else       g_w2[row] = t;
    }
}

// Tiled SGEMM: out[m, n] = -(x2[m] - 2 * sum_k X[m,k]*W[n,k] + w2[n]) / F
// BM=128, BN=64, BK=16, 256 threads, 8x4 micro-tile per thread.
__global__ void __launch_bounds__(256) gemm_kernel(const float* __restrict__ X,
                                                   const float* __restrict__ W,
                                                   float* __restrict__ out,
                                                   int M, int N) {
    __shared__ __align__(16) float As[BK][BM + 4];  // transposed: As[k][m]
    __shared__ __align__(16) float Bs[BK][BN + 4];  // transposed: Bs[k][n]

    int tid = threadIdx.x;
    int tx = tid & 15;   // 0..15 -> 4 output cols each
    int ty = tid >> 4;   // 0..15 -> 8 output rows each
    int m0 = blockIdx.y * BM;
    int n0 = blockIdx.x * BN;

    float acc[8][4] = {};

    const float* Xp = X + (size_t)m0 * K_DIM;

    for (int k0 = 0; k0 < K_DIM; k0 += BK) {
        // X tile: 128 rows x 16 cols = 512 float4; 2 per thread.
#pragma unroll
        for (int i = 0; i < 2; ++i) {
            int idx = tid * 2 + i;
            int r = idx >> 2;          // 0..127
            int c4 = idx & 3;          // which float4 within the 16 cols
            float4 v = *reinterpret_cast<const float4*>(
                Xp + (size_t)r * K_DIM + k0 + c4 * 4);
            As[c4 * 4 + 0][r] = v.x;
            As[c4 * 4 + 1][r] = v.y;
            As[c4 * 4 + 2][r] = v.z;
            As[c4 * 4 + 3][r] = v.w;
        }
        // W tile: 64 rows x 16 cols = 256 float4; 1 per thread. Guard n >= N.
        {
            int r = tid >> 2;          // 0..63
            int c4 = tid & 3;
            int n = n0 + r;
            float4 v = make_float4(0.f, 0.f, 0.f, 0.f);
            if (n < N)
                v = *reinterpret_cast<const float4*>(
                    W + (size_t)n * K_DIM + k0 + c4 * 4);
            Bs[c4 * 4 + 0][r] = v.x;
            Bs[c4 * 4 + 1][r] = v.y;
            Bs[c4 * 4 + 2][r] = v.z;
            Bs[c4 * 4 + 3][r] = v.w;
        }
        __syncthreads();

#pragma unroll
        for (int k = 0; k < BK; ++k) {
            float4 a0 = *reinterpret_cast<const float4*>(&As[k][ty * 8]);
            float4 a1 = *reinterpret_cast<const float4*>(&As[k][ty * 8 + 4]);
            float4 b  = *reinterpret_cast<const float4*>(&Bs[k][tx * 4]);
            float am[8] = {a0.x, a0.y, a0.z, a0.w, a1.x, a1.y, a1.z, a1.w};
            float bn[4] = {b.x, b.y, b.z, b.w};
#pragma unroll
            for (int i = 0; i < 8; ++i)
#pragma unroll
                for (int j = 0; j < 4; ++j) acc[i][j] += am[i] * bn[j];
        }
        __syncthreads();
    }

    // Epilogue: fuse the norms.
    float x2v[8], w2v[4];
#pragma unroll
    for (int i = 0; i < 8; ++i) x2v[i] = g_x2[m0 + ty * 8 + i];
#pragma unroll
    for (int j = 0; j < 4; ++j) {
        int n = n0 + tx * 4 + j;
        w2v[j] = (n < N) ? g_w2[n] : 0.f;
    }
#pragma unroll
    for (int i = 0; i < 8; ++i) {
        int m = m0 + ty * 8 + i;
#pragma unroll
        for (int j = 0; j < 4; ++j) {
            int n = n0 + tx * 4 + j;
            if (n < N)
                out[(size_t)m * N + n] =
                    -(x2v[i] - 2.f * acc[i][j] + w2v[j]) * INV_F;
        }
    }
}

extern "C" void kernel_launch(void* const* d_in, const int* in_sizes, int n_in,
                              void* d_out, int out_size) {
    const float* x = (const float*)d_in[0];
    const float* w = (const float*)d_in[1];
    float* out = (float*)d_out;
    int M = in_sizes[0] / K_DIM;   // 16384
    int N = in_sizes[1] / K_DIM;   // 1000

    rowsq_kernel<<<M, 128>>>(x, 1);
    rowsq_kernel<<<N, 128>>>(w, 0);

    dim3 grid((N + BN - 1) / BN, M / BM);
    gemm_kernel<<<grid, 256>>>(x, w, out, M, N);
}

// round 3
// speedup vs baseline: 7.2316x; 7.2316x over previous
#include <cuda_runtime.h>
#include <cuda_bf16.h>
#include <cstdint>

#define K_DIM 2048
#define INV_F (1.0f / 2048.0f)
#define M_TOTAL 16384
#define N_PAD 1024
#define BM 128
#define BN 128
#define BK 32
#define STAGES 4
#define SA_BYTES 80                         // 32 bf16 (64B) + 16B pad: stride 5 mod 8 in 16B banks
#define TILE_BYTES (128 * SA_BYTES)         // 10240 per operand tile
#define STAGE_BYTES (2 * TILE_BYTES)        // 20480
#define DYN_SMEM (STAGES * STAGE_BYTES)     // 81920

// Scratch (no device allocation allowed)
__device__ __align__(16) __nv_bfloat16 g_xb[(size_t)M_TOTAL * K_DIM];
__device__ __align__(16) __nv_bfloat16 g_wb[(size_t)N_PAD * K_DIM];
__device__ float g_x2[M_TOTAL];
__device__ float g_w2[N_PAD];

__device__ __forceinline__ uint32_t smem_u32(const void* p) {
    return (uint32_t)__cvta_generic_to_shared(p);
}

__device__ __forceinline__ void ldm_x4(uint32_t* r, uint32_t addr) {
    asm volatile("ldmatrix.sync.aligned.m8n8.x4.shared.b16 {%0,%1,%2,%3}, [%4];"
                 : "=r"(r[0]), "=r"(r[1]), "=r"(r[2]), "=r"(r[3]) : "r"(addr));
}

__device__ __forceinline__ void mma_bf16(float* d, const uint32_t* a, const uint32_t* b) {
    asm volatile(
        "mma.sync.aligned.m16n8k16.row.col.f32.bf16.bf16.f32 "
        "{%0,%1,%2,%3}, {%4,%5,%6,%7}, {%8,%9}, {%0,%1,%2,%3};"
        : "+f"(d[0]), "+f"(d[1]), "+f"(d[2]), "+f"(d[3])
        : "r"(a[0]), "r"(a[1]), "r"(a[2]), "r"(a[3]), "r"(b[0]), "r"(b[1]));
}

// ---------------- fp32 -> bf16 conversion, fused row sum-of-squares ----------------

__global__ void __launch_bounds__(256) convert_x_kernel(const float* __restrict__ x) {
    int row = blockIdx.x;
    const float4* src = reinterpret_cast<const float4*>(x + (size_t)row * K_DIM);
    uint2* dst = reinterpret_cast<uint2*>(g_xb + (size_t)row * K_DIM);
    float s = 0.f;
#pragma unroll
    for (int i = 0; i < 2; ++i) {
        int idx = threadIdx.x + i * 256;
        float4 v = src[idx];
        s += v.x * v.x + v.y * v.y + v.z * v.z + v.w * v.w;
        __nv_bfloat162 p0 = __float22bfloat162_rn(make_float2(v.x, v.y));
        __nv_bfloat162 p1 = __float22bfloat162_rn(make_float2(v.z, v.w));
        uint2 o;
        o.x = *reinterpret_cast<uint32_t*>(&p0);
        o.y = *reinterpret_cast<uint32_t*>(&p1);
        dst[idx] = o;
    }
#pragma unroll
    for (int o = 16; o > 0; o >>= 1) s += __shfl_xor_sync(0xffffffffu, s, o);
    __shared__ float red[8];
    if ((threadIdx.x & 31) == 0) red[threadIdx.x >> 5] = s;
    __syncthreads();
    if (threadIdx.x == 0) {
        float t = 0.f;
#pragma unroll
        for (int i = 0; i < 8; ++i) t += red[i];
        g_x2[row] = t;
    }
}

__global__ void __launch_bounds__(256) convert_w_kernel(const float* __restrict__ w, int N) {
    int row = blockIdx.x;
    uint2* dst = reinterpret_cast<uint2*>(g_wb + (size_t)row * K_DIM);
    if (row >= N) {
#pragma unroll
        for (int i = 0; i < 2; ++i) dst[threadIdx.x + i * 256] = make_uint2(0u, 0u);
        if (threadIdx.x == 0) g_w2[row] = 0.f;
        return;
    }
    const float4* src = reinterpret_cast<const float4*>(w + (size_t)row * K_DIM);
    float s = 0.f;
#pragma unroll
    for (int i = 0; i < 2; ++i) {
        int idx = threadIdx.x + i * 256;
        float4 v = src[idx];
        s += v.x * v.x + v.y * v.y + v.z * v.z + v.w * v.w;
        __nv_bfloat162 p0 = __float22bfloat162_rn(make_float2(v.x, v.y));
        __nv_bfloat162 p1 = __float22bfloat162_rn(make_float2(v.z, v.w));
        uint2 o;
        o.x = *reinterpret_cast<uint32_t*>(&p0);
        o.y = *reinterpret_cast<uint32_t*>(&p1);
        dst[idx] = o;
    }
#pragma unroll
    for (int o = 16; o > 0; o >>= 1) s += __shfl_xor_sync(0xffffffffu, s, o);
    __shared__ float red[8];
    if ((threadIdx.x & 31) == 0) red[threadIdx.x >> 5] = s;
    __syncthreads();
    if (threadIdx.x == 0) {
        float t = 0.f;
#pragma unroll
        for (int i = 0; i < 8; ++i) t += red[i];
        g_w2[row] = t;
    }
}

// ---------------- mma.sync bf16 GEMM ----------------
// out[m,n] = -(x2[m] - 2*sum_k X[m,k]W[n,k] + w2[n]) / F
// CTA 128x128x32, 8 warps (2 M x 4 N), warp tile 64x32, 4-stage cp.async.

__device__ __forceinline__ void load_stage(uint32_t base, int s, int kt,
                                           int m0, int n0, int tid) {
    uint32_t sb = base + (uint32_t)s * STAGE_BYTES;
    const __nv_bfloat16* xa = g_xb + (size_t)m0 * K_DIM + kt * BK;
    const __nv_bfloat16* wb = g_wb + (size_t)n0 * K_DIM + kt * BK;
#pragma unroll
    for (int i = 0; i < 4; ++i) {
        int idx = tid + i * 256;                 // 0..1023
        int op = idx >> 9;                       // 0 = A, 1 = B
        int r = (idx >> 2) & 127;
        int c = idx & 3;
        uint32_t dst = sb + (uint32_t)op * TILE_BYTES + (uint32_t)(r * SA_BYTES + c * 16);
        const __nv_bfloat16* src = (op ? wb : xa) + (size_t)r * K_DIM + c * 8;
        asm volatile("cp.async.cg.shared.global [%0], [%1], 16;"
                     :: "r"(dst), "l"(src) : "memory");
    }
    asm volatile("cp.async.commit_group;" ::: "memory");
}

__global__ void __launch_bounds__(256, 2) gemm_mma_kernel(float* __restrict__ out, int N) {
    extern __shared__ __align__(16) char dyn_smem[];
    __shared__ float s_x2[BM];
    __shared__ float s_w2[BN];

    const uint32_t base = smem_u32(dyn_smem);
    const int tid = threadIdx.x;
    const int wid = tid >> 5, lid = tid & 31;
    const int m0 = blockIdx.y * BM;
    const int n0 = blockIdx.x * BN;
    const int mw = (wid >> 2) * 64;    // warp M offset
    const int nw = (wid & 3) * 32;     // warp N offset

    if (tid < BM) s_x2[tid] = g_x2[m0 + tid];
    else          s_w2[tid - BM] = g_w2[n0 + tid - BM];

    // Prologue: prefetch STAGES-1 stages.
#pragma unroll
    for (int s = 0; s < STAGES - 1; ++s) load_stage(base, s, s, m0, n0, tid);

    float acc[4][4][4] = {};

    // Fragment smem addresses (lane-dependent parts precomputed).
    // A: row = mw + (lid & 15), chunk byte = (lid >> 4) * 16
    // B: row = nw + (lid & 7) + ((lid >> 4) << 3), chunk byte = ((lid >> 3) & 1) * 16
    const uint32_t a_lane = (uint32_t)((mw + (lid & 15)) * SA_BYTES + (lid >> 4) * 16);
    const uint32_t b_lane = (uint32_t)TILE_BYTES +
        (uint32_t)((nw + (lid & 7) + ((lid >> 4) << 3)) * SA_BYTES + ((lid >> 3) & 1) * 16);

    const int NITER = K_DIM / BK;  // 64
    for (int kt = 0; kt < NITER; ++kt) {
        asm volatile("cp.async.wait_group %0;" :: "n"(STAGES - 2) : "memory");
        __syncthreads();
        uint32_t sb = base + (uint32_t)(kt % STAGES) * STAGE_BYTES;

#pragma unroll
        for (int ks = 0; ks < 2; ++ks) {
            uint32_t a_frag[4][4], b_frag[2][4];
#pragma unroll
            for (int mt = 0; mt < 4; ++mt)
                ldm_x4(a_frag[mt], sb + a_lane + (uint32_t)(mt * 16 * SA_BYTES + ks * 32));
#pragma unroll
            for (int nt = 0; nt < 2; ++nt)
                ldm_x4(b_frag[nt], sb + b_lane + (uint32_t)(nt * 16 * SA_BYTES + ks * 32));
#pragma unroll
            for (int mt = 0; mt < 4; ++mt)
#pragma unroll
                for (int nt = 0; nt < 4; ++nt)
                    mma_bf16(acc[mt][nt], a_frag[mt], &b_frag[nt >> 1][(nt & 1) * 2]);
        }

        int kl = kt + STAGES - 1;
        if (kl < NITER) load_stage(base, kl % STAGES, kl, m0, n0, tid);
        else asm volatile("cp.async.commit_group;" ::: "memory");
    }

    // Epilogue: fused norms; thread (lane l) owns rows l/4, l/4+8 and col pairs 2*(l%4).
    const int q = lid >> 2, rr = lid & 3;
#pragma unroll
    for (int mt = 0; mt < 4; ++mt) {
        int r0 = mw + mt * 16 + q;
        float x2a = s_x2[r0], x2b = s_x2[r0 + 8];
        float* orow0 = out + (size_t)(m0 + r0) * N;
        float* orow1 = orow0 + (size_t)8 * N;
#pragma unroll
        for (int nt = 0; nt < 4; ++nt) {
            int cl = nw + nt * 8 + 2 * rr;      // local col (even)
            int col = n0 + cl;
            if (col < N) {
                float w2a = s_w2[cl], w2b = s_w2[cl + 1];
                float2 v0, v1;
                v0.x = (2.0f * INV_F) * acc[mt][nt][0] - (x2a + w2a) * INV_F;
                v0.y = (2.0f * INV_F) * acc[mt][nt][1] - (x2a + w2b) * INV_F;
                v1.x = (2.0f * INV_F) * acc[mt][nt][2] - (x2b + w2a) * INV_F;
                v1.y = (2.0f * INV_F) * acc[mt][nt][3] - (x2b + w2b) * INV_F;
                *reinterpret_cast<float2*>(orow0 + col) = v0;
                *reinterpret_cast<float2*>(orow1 + col) = v1;
            }
        }
    }
}

extern "C" void kernel_launch(void* const* d_in, const int* in_sizes, int n_in,
                              void* d_out, int out_size) {
    const float* x = (const float*)d_in[0];
    const float* w = (const float*)d_in[1];
    float* out = (float*)d_out;
    int M = in_sizes[0] / K_DIM;   // 16384
    int N = in_sizes[1] / K_DIM;   // 1000

    convert_x_kernel<<<M, 256>>>(x);
    convert_w_kernel<<<N_PAD, 256>>>(w, N);

    cudaFuncSetAttribute(gemm_mma_kernel,
                         cudaFuncAttributeMaxDynamicSharedMemorySize, DYN_SMEM);
    gemm_mma_kernel<<<dim3(N_PAD / BN, M / BM), 256, DYN_SMEM>>>(out, N);
}